// round 12
// baseline (speedup 1.0000x reference)
#include <cuda_runtime.h>

// B=1, H=16, S=4096, D=64, fp32, NO softmax.
// (Q K^T) V == Q (K^T V);  K^T V is [64x64] per head -> 64x fewer FLOPs.
// R12: tf32x3 tensor-core GEMMs with hi/lo tf32 planes PACKED into u64 words:
// one LDS.64 per fragment element fetches both planes (halves inner-loop LDS).
// Q is pre-split at staging; M is pre-split+packed in GMEM by reduce_m.
#define HEADS 16
#define SEQ   4096
#define DIM   64
#define NSPLIT 32
#define CHUNK (SEQ / NSPLIT)   // 128 rows per partial block

__device__ __align__(16) float              g_partial[HEADS * NSPLIT * DIM * DIM]; // 8 MB
__device__ __align__(16) unsigned long long g_Mpk[HEADS * DIM * DIM];              // 512 KB

// ---- tf32 helpers ---------------------------------------------------------
__device__ __forceinline__ void split_tf32(float x, unsigned& hi, unsigned& lo) {
    asm("cvt.rna.tf32.f32 %0, %1;" : "=r"(hi) : "f"(x));
    const float hf = __uint_as_float(hi);
    const float l  = x - hf;
    asm("cvt.rna.tf32.f32 %0, %1;" : "=r"(lo) : "f"(l));
}
__device__ __forceinline__ unsigned long long pack_tf32(float x) {
    unsigned hi, lo;
    split_tf32(x, hi, lo);
    return (unsigned long long)hi | ((unsigned long long)lo << 32);
}
__device__ __forceinline__ void mma_tf32(float* d, const unsigned* a, const unsigned* b) {
    asm("mma.sync.aligned.m16n8k8.row.col.f32.tf32.tf32.f32 "
        "{%0,%1,%2,%3}, {%4,%5,%6,%7}, {%8,%9}, {%0,%1,%2,%3};"
        : "+f"(d[0]), "+f"(d[1]), "+f"(d[2]), "+f"(d[3])
        : "r"(a[0]), "r"(a[1]), "r"(a[2]), "r"(a[3]), "r"(b[0]), "r"(b[1]));
}
// issue the tf32x3 compensated product pair-wise from packed fragments
__device__ __forceinline__ void mma_x3(float* acc,
                                       const unsigned long long* a4,   // 4 packed A elems
                                       const unsigned long long* b2) { // 2 packed B elems
    unsigned ah[4], al[4], bh[2], bl[2];
    #pragma unroll
    for (int i = 0; i < 4; i++) { ah[i] = (unsigned)a4[i]; al[i] = (unsigned)(a4[i] >> 32); }
    #pragma unroll
    for (int i = 0; i < 2; i++) { bh[i] = (unsigned)b2[i]; bl[i] = (unsigned)(b2[i] >> 32); }
    mma_tf32(acc, ah, bh);
    mma_tf32(acc, ah, bl);
    mma_tf32(acc, al, bh);
}

// row stride of packed planes in u64 units: 68 u64 = 136 u32 == 8 (mod 32)
// -> all (8t+2g) fragment gathers are bank-conflict-free for LDS.64.
#define PSTR 68

// ---------------------------------------------------------------------------
// Kernel 1: partial M = K_chunk^T @ V_chunk.  grid = HEADS*NSPLIT, 256 thr.
// 8 warps: (wid&3) -> d1 block of 16; (wid>>2) -> d2 block of 32 (nt=4).
// Packed planes in smem; staging SW-pipelined through registers.
// ---------------------------------------------------------------------------
__global__ __launch_bounds__(256) void ktv_partial(const float* __restrict__ Kp,
                                                   const float* __restrict__ Vp) {
    const int h  = blockIdx.x / NSPLIT;
    const int sp = blockIdx.x % NSPLIT;
    const float* Kh = Kp + ((size_t)h * SEQ + (size_t)sp * CHUNK) * DIM;
    const float* Vh = Vp + ((size_t)h * SEQ + (size_t)sp * CHUNK) * DIM;

    __shared__ __align__(16) unsigned long long Kpk[32][PSTR];   // 17.4 KB
    __shared__ __align__(16) unsigned long long Vpk[32][PSTR];   // 17.4 KB

    const int tid  = threadIdx.x;
    const int wid  = tid >> 5;
    const int lane = tid & 31;
    const int g = lane >> 2;      // 0..7
    const int t = lane & 3;       // 0..3
    const int d1_0 = (wid & 3) * 16;
    const int d2_0 = (wid >> 2) * 32;

    // per-thread staging slots: i = tid + j*256 -> row i>>4, col4 (i&15)<<2
    const int sr0 = tid >> 4,          sc0 = (tid & 15) << 2;
    const int sr1 = (tid + 256) >> 4;

    float4 kbuf[2], vbuf[2];
    float acc[4][4] = {};

    auto stash = [&](float4 kv, float4 vv, int r) {
        ulonglong2 p;
        p.x = pack_tf32(kv.x); p.y = pack_tf32(kv.y);
        *(ulonglong2*)&Kpk[r][sc0] = p;
        p.x = pack_tf32(kv.z); p.y = pack_tf32(kv.w);
        *(ulonglong2*)&Kpk[r][sc0 + 2] = p;
        p.x = pack_tf32(vv.x); p.y = pack_tf32(vv.y);
        *(ulonglong2*)&Vpk[r][sc0] = p;
        p.x = pack_tf32(vv.z); p.y = pack_tf32(vv.w);
        *(ulonglong2*)&Vpk[r][sc0 + 2] = p;
    };

    // prologue: tile 0
    kbuf[0] = *(const float4*)&Kh[(size_t)sr0 * DIM + sc0];
    vbuf[0] = *(const float4*)&Vh[(size_t)sr0 * DIM + sc0];
    kbuf[1] = *(const float4*)&Kh[(size_t)sr1 * DIM + sc0];
    vbuf[1] = *(const float4*)&Vh[(size_t)sr1 * DIM + sc0];
    stash(kbuf[0], vbuf[0], sr0);
    stash(kbuf[1], vbuf[1], sr1);
    __syncthreads();

    #pragma unroll
    for (int ph = 0; ph < CHUNK / 32; ph++) {
        if (ph < CHUNK / 32 - 1) {
            const int t0 = (ph + 1) * 32;
            kbuf[0] = *(const float4*)&Kh[(size_t)(t0 + sr0) * DIM + sc0];
            vbuf[0] = *(const float4*)&Vh[(size_t)(t0 + sr0) * DIM + sc0];
            kbuf[1] = *(const float4*)&Kh[(size_t)(t0 + sr1) * DIM + sc0];
            vbuf[1] = *(const float4*)&Vh[(size_t)(t0 + sr1) * DIM + sc0];
        }

        #pragma unroll
        for (int ks = 0; ks < 32; ks += 8) {
            unsigned long long a4[4];
            a4[0] = Kpk[ks + t][d1_0 + g];
            a4[1] = Kpk[ks + t][d1_0 + g + 8];
            a4[2] = Kpk[ks + t + 4][d1_0 + g];
            a4[3] = Kpk[ks + t + 4][d1_0 + g + 8];
            #pragma unroll
            for (int nt = 0; nt < 4; nt++) {
                const int col = d2_0 + nt * 8 + g;
                unsigned long long b2[2];
                b2[0] = Vpk[ks + t][col];
                b2[1] = Vpk[ks + t + 4][col];
                mma_x3(acc[nt], a4, b2);
            }
        }
        __syncthreads();

        if (ph < CHUNK / 32 - 1) {
            stash(kbuf[0], vbuf[0], sr0);
            stash(kbuf[1], vbuf[1], sr1);
            __syncthreads();
        }
    }

    float* outp = g_partial + ((size_t)h * NSPLIT + sp) * DIM * DIM;
    #pragma unroll
    for (int nt = 0; nt < 4; nt++) {
        const int col = d2_0 + nt * 8 + 2 * t;
        const int row = d1_0 + g;
        *(float2*)&outp[row * DIM + col]       = make_float2(acc[nt][0], acc[nt][1]);
        *(float2*)&outp[(row + 8) * DIM + col] = make_float2(acc[nt][2], acc[nt][3]);
    }
}

// ---------------------------------------------------------------------------
// Kernel 2: reduce NSPLIT partials -> packed tf32 hi/lo u64 planes in GMEM.
// ---------------------------------------------------------------------------
__global__ __launch_bounds__(256) void reduce_m() {
    const int idx = blockIdx.x * 256 + threadIdx.x;   // float4 index
    if (idx >= HEADS * DIM * DIM / 4) return;
    const int h = idx / (DIM * DIM / 4);
    const int e = idx % (DIM * DIM / 4);
    float4 s = make_float4(0.f, 0.f, 0.f, 0.f);
    #pragma unroll
    for (int p = 0; p < NSPLIT; p++) {
        const float4 tv = *(const float4*)&g_partial[(((size_t)h * NSPLIT + p) * DIM * DIM) + e * 4];
        s.x += tv.x; s.y += tv.y; s.z += tv.z; s.w += tv.w;
    }
    ulonglong2 p;
    p.x = pack_tf32(s.x); p.y = pack_tf32(s.y);
    *(ulonglong2*)&g_Mpk[(size_t)idx * 4] = p;
    p.x = pack_tf32(s.z); p.y = pack_tf32(s.w);
    *(ulonglong2*)&g_Mpk[(size_t)idx * 4 + 2] = p;
}

// ---------------------------------------------------------------------------
// Kernel 3: out = Q @ M.  Block = 64 q-rows x 64 cols, 256 thr (8 warps).
// (wid&1) -> 32-row group (mt=2), (wid>>1) -> 16-col group (nt=2).
// Both Q and M live as packed u64 planes in smem; M pre-packed in GMEM,
// Q packed at staging. Inner loop: 12 LDS.64 + 12 MMA, zero split ALU.
// Dynamic smem: 2 * 64*68*8 = 69.6 KB.
// ---------------------------------------------------------------------------
#define QROWS 64
__global__ __launch_bounds__(256) void qm_gemm(const float* __restrict__ Qp,
                                               float* __restrict__ Op) {
    extern __shared__ __align__(16) char smem_raw[];
    unsigned long long (*Mpk_s)[PSTR] = (unsigned long long (*)[PSTR])smem_raw;
    unsigned long long (*Qpk_s)[PSTR] =
        (unsigned long long (*)[PSTR])(smem_raw + DIM * PSTR * 8);

    const int h  = blockIdx.x >> 6;            // 64 blocks per head
    const int r0 = (blockIdx.x & 63) * QROWS;

    const int tid  = threadIdx.x;
    const int wid  = tid >> 5;
    const int lane = tid & 31;
    const int g = lane >> 2;
    const int t = lane & 3;
    const int rw = (wid & 1) * 32;     // q-row group of 32
    const int c0 = (wid >> 1) * 16;    // out col group of 16

    const float* Qh = Qp + ((size_t)h * SEQ + r0) * DIM;
    const unsigned long long* MpkG = g_Mpk + (size_t)h * DIM * DIM;

    // stage M packed planes (4096 u64 = 2048 ulonglong2; 8 per thread)
    #pragma unroll
    for (int i = tid; i < DIM * 32; i += 256) {
        const int r  = i >> 5;
        const int c2 = (i & 31) << 1;
        *(ulonglong2*)&Mpk_s[r][c2] = *(const ulonglong2*)&MpkG[r * DIM + c2];
    }
    // stage + pack Q tile (1024 float4; 4 per thread)
    #pragma unroll
    for (int i = tid; i < QROWS * 16; i += 256) {
        const int r  = i >> 4;
        const int c4 = (i & 15) << 2;
        const float4 qv = *(const float4*)&Qh[(size_t)r * DIM + c4];
        ulonglong2 p;
        p.x = pack_tf32(qv.x); p.y = pack_tf32(qv.y);
        *(ulonglong2*)&Qpk_s[r][c4] = p;
        p.x = pack_tf32(qv.z); p.y = pack_tf32(qv.w);
        *(ulonglong2*)&Qpk_s[r][c4 + 2] = p;
    }
    __syncthreads();

    float acc[2][2][4] = {};

    #pragma unroll
    for (int ks = 0; ks < DIM; ks += 8) {
        unsigned long long a4[2][4];
        #pragma unroll
        for (int mt = 0; mt < 2; mt++) {
            const int row = rw + mt * 16;
            a4[mt][0] = Qpk_s[row + g][ks + t];
            a4[mt][1] = Qpk_s[row + g + 8][ks + t];
            a4[mt][2] = Qpk_s[row + g][ks + t + 4];
            a4[mt][3] = Qpk_s[row + g + 8][ks + t + 4];
        }
        #pragma unroll
        for (int nt = 0; nt < 2; nt++) {
            const int col = c0 + nt * 8 + g;
            unsigned long long b2[2];
            b2[0] = Mpk_s[ks + t][col];
            b2[1] = Mpk_s[ks + t + 4][col];
            #pragma unroll
            for (int mt = 0; mt < 2; mt++)
                mma_x3(acc[mt][nt], a4[mt], b2);
        }
    }

    float* Oh = Op + ((size_t)h * SEQ + r0) * DIM;
    #pragma unroll
    for (int mt = 0; mt < 2; mt++) {
        #pragma unroll
        for (int nt = 0; nt < 2; nt++) {
            const int col = c0 + nt * 8 + 2 * t;
            const int row = rw + mt * 16 + g;
            *(float2*)&Oh[(size_t)row * DIM + col]       = make_float2(acc[mt][nt][0], acc[mt][nt][1]);
            *(float2*)&Oh[(size_t)(row + 8) * DIM + col] = make_float2(acc[mt][nt][2], acc[mt][nt][3]);
        }
    }
}

// ---------------------------------------------------------------------------
extern "C" void kernel_launch(void* const* d_in, const int* in_sizes, int n_in,
                              void* d_out, int out_size) {
    const float* q = (const float*)d_in[0];
    const float* k = (const float*)d_in[1];
    const float* v = (const float*)d_in[2];
    float* out = (float*)d_out;

    const int qm_smem = 2 * DIM * PSTR * 8;   // 69.6 KB
    static int attr_done = 0;   // idempotent attribute set (not a work guard)
    if (!attr_done) {
        cudaFuncSetAttribute(qm_gemm, cudaFuncAttributeMaxDynamicSharedMemorySize, qm_smem);
        attr_done = 1;
    }

    ktv_partial<<<HEADS * NSPLIT, 256>>>(k, v);
    reduce_m<<<(HEADS * DIM * DIM / 4 + 255) / 256, 256>>>();
    qm_gemm<<<HEADS * (SEQ / QROWS), 256, qm_smem>>>(q, out);
}

// round 14
// speedup vs baseline: 1.4491x; 1.4491x over previous
#include <cuda_runtime.h>
#include <cuda_bf16.h>

// B=1, H=16, S=4096, D=64, fp32, NO softmax.
// (Q K^T) V == Q (K^T V);  K^T V is [64x64] per head -> 64x fewer FLOPs.
// R13: bf16x3 compensated tensor-core GEMMs with mma.m16n8k16:
//   x = hi + lo (both bf16); A*B ~= Ah*Bh + Ah*Bl + Al*Bh (fp32 accum)
//   error ~2^-18 per element -> rel_err ~1e-5 (threshold 1e-3).
// k16 halves MMA count vs tf32-k8; bf16 k-pairs pack 2 elems per u32 word,
// halving fragment LDS with plain 32-bit loads (no u64 extraction).
#define HEADS 16
#define SEQ   4096
#define DIM   64
#define NSPLIT 32
#define CHUNK (SEQ / NSPLIT)   // 128 rows per partial block

__device__ __align__(16) float g_partial[HEADS * NSPLIT * DIM * DIM];  // 8 MB
__device__ __align__(16) float g_M[HEADS * DIM * DIM];                 // 256 KB

// ---- bf16 split/pack helpers ----------------------------------------------
// word = bf16(x0) | bf16(x1)<<16   (x0 = even k, x1 = odd k)
__device__ __forceinline__ void split_bf16(float x, float& hi_f, __nv_bfloat16& hi,
                                           __nv_bfloat16& lo) {
    hi = __float2bfloat16_rn(x);
    hi_f = __bfloat162float(hi);
    lo = __float2bfloat16_rn(x - hi_f);
}
__device__ __forceinline__ void pack2(float x0, float x1, unsigned& whi, unsigned& wlo) {
    float h0f, h1f;
    __nv_bfloat16 h0, l0, h1, l1;
    split_bf16(x0, h0f, h0, l0);
    split_bf16(x1, h1f, h1, l1);
    __nv_bfloat162 ph = __halves2bfloat162(h0, h1);
    __nv_bfloat162 pl = __halves2bfloat162(l0, l1);
    whi = *(unsigned*)&ph;
    wlo = *(unsigned*)&pl;
}
__device__ __forceinline__ void mma_bf16(float* d, const unsigned* a, const unsigned* b) {
    asm("mma.sync.aligned.m16n8k16.row.col.f32.bf16.bf16.f32 "
        "{%0,%1,%2,%3}, {%4,%5,%6,%7}, {%8,%9}, {%0,%1,%2,%3};"
        : "+f"(d[0]), "+f"(d[1]), "+f"(d[2]), "+f"(d[3])
        : "r"(a[0]), "r"(a[1]), "r"(a[2]), "r"(a[3]), "r"(b[0]), "r"(b[1]));
}
__device__ __forceinline__ void mma_x3(float* acc, const unsigned* ah, const unsigned* al,
                                       const unsigned* bh, const unsigned* bl) {
    mma_bf16(acc, ah, bh);
    mma_bf16(acc, ah, bl);
    mma_bf16(acc, al, bh);
}

#define KSTR 72   // u32 row stride of k-pair planes: ==8 mod 32 -> (8sp+g) conflict-free

// ---------------------------------------------------------------------------
// Kernel 1: partial M = K_chunk^T @ V_chunk.  grid = HEADS*NSPLIT, 256 thr.
// A = K^T [d1 x s], B = V [s x d2]; k dim = s. Planes indexed [sp=s/2][d]:
// word = (bf16 of s=2sp) | (bf16 of s=2sp+1)<<16, exactly the mma k-pair.
// 8 warps: (wid&3) -> d1 block of 16; (wid>>2) -> d2 block of 32 (nt=4).
// Staging SW-pipelined through registers (2 float4 per matrix per thread).
// ---------------------------------------------------------------------------
__global__ __launch_bounds__(256) void ktv_partial(const float* __restrict__ Kp,
                                                   const float* __restrict__ Vp) {
    const int h  = blockIdx.x / NSPLIT;
    const int sp_ = blockIdx.x % NSPLIT;
    const float* Kh = Kp + ((size_t)h * SEQ + (size_t)sp_ * CHUNK) * DIM;
    const float* Vh = Vp + ((size_t)h * SEQ + (size_t)sp_ * CHUNK) * DIM;

    __shared__ __align__(16) unsigned Khi[16][KSTR], Klo[16][KSTR];   // 9.2 KB
    __shared__ __align__(16) unsigned Vhi[16][KSTR], Vlo[16][KSTR];   // 9.2 KB

    const int tid  = threadIdx.x;
    const int wid  = tid >> 5;
    const int lane = tid & 31;
    const int g = lane >> 2;      // 0..7
    const int t = lane & 3;       // 0..3
    const int d1_0 = (wid & 3) * 16;
    const int d2_0 = (wid >> 2) * 32;

    // staging slot: thread -> s-pair sp (0..15), cols c4..c4+3
    const int sp = tid >> 4;
    const int c4 = (tid & 15) << 2;

    float4 k0, k1, v0, v1;   // rows 2sp, 2sp+1
    float acc[4][4] = {};

    auto stash = [&]() {
        uint4 whi, wlo;
        pack2(k0.x, k1.x, whi.x, wlo.x);
        pack2(k0.y, k1.y, whi.y, wlo.y);
        pack2(k0.z, k1.z, whi.z, wlo.z);
        pack2(k0.w, k1.w, whi.w, wlo.w);
        *(uint4*)&Khi[sp][c4] = whi;
        *(uint4*)&Klo[sp][c4] = wlo;
        pack2(v0.x, v1.x, whi.x, wlo.x);
        pack2(v0.y, v1.y, whi.y, wlo.y);
        pack2(v0.z, v1.z, whi.z, wlo.z);
        pack2(v0.w, v1.w, whi.w, wlo.w);
        *(uint4*)&Vhi[sp][c4] = whi;
        *(uint4*)&Vlo[sp][c4] = wlo;
    };
    auto fetch = [&](int t0) {
        k0 = *(const float4*)&Kh[(size_t)(t0 + 2 * sp) * DIM + c4];
        k1 = *(const float4*)&Kh[(size_t)(t0 + 2 * sp + 1) * DIM + c4];
        v0 = *(const float4*)&Vh[(size_t)(t0 + 2 * sp) * DIM + c4];
        v1 = *(const float4*)&Vh[(size_t)(t0 + 2 * sp + 1) * DIM + c4];
    };

    fetch(0);
    stash();
    __syncthreads();

    #pragma unroll
    for (int ph = 0; ph < CHUNK / 32; ph++) {
        if (ph < CHUNK / 32 - 1) fetch((ph + 1) * 32);   // overlap with MMA below

        #pragma unroll
        for (int ks = 0; ks < 2; ks++) {                 // two k16 slabs per tile
            const int sb = ks * 8;
            unsigned ah[4], al[4];
            ah[0] = Khi[sb + t][d1_0 + g];         al[0] = Klo[sb + t][d1_0 + g];
            ah[1] = Khi[sb + t][d1_0 + g + 8];     al[1] = Klo[sb + t][d1_0 + g + 8];
            ah[2] = Khi[sb + t + 4][d1_0 + g];     al[2] = Klo[sb + t + 4][d1_0 + g];
            ah[3] = Khi[sb + t + 4][d1_0 + g + 8]; al[3] = Klo[sb + t + 4][d1_0 + g + 8];
            #pragma unroll
            for (int nt = 0; nt < 4; nt++) {
                const int col = d2_0 + nt * 8 + g;
                unsigned bh[2], bl[2];
                bh[0] = Vhi[sb + t][col];     bl[0] = Vlo[sb + t][col];
                bh[1] = Vhi[sb + t + 4][col]; bl[1] = Vlo[sb + t + 4][col];
                mma_x3(acc[nt], ah, al, bh, bl);
            }
        }
        __syncthreads();   // MMA reads done before smem overwrite

        if (ph < CHUNK / 32 - 1) {
            stash();
            __syncthreads();
        }
    }

    float* outp = g_partial + ((size_t)h * NSPLIT + sp_) * DIM * DIM;
    #pragma unroll
    for (int nt = 0; nt < 4; nt++) {
        const int col = d2_0 + nt * 8 + 2 * t;
        const int row = d1_0 + g;
        *(float2*)&outp[row * DIM + col]       = make_float2(acc[nt][0], acc[nt][1]);
        *(float2*)&outp[(row + 8) * DIM + col] = make_float2(acc[nt][2], acc[nt][3]);
    }
}

// ---------------------------------------------------------------------------
// Kernel 2: reduce NSPLIT partials -> g_M (plain fp32; qm packs at staging).
// ---------------------------------------------------------------------------
__global__ __launch_bounds__(256) void reduce_m() {
    const int idx = blockIdx.x * 256 + threadIdx.x;   // float4 index
    if (idx >= HEADS * DIM * DIM / 4) return;
    const int h = idx / (DIM * DIM / 4);
    const int e = idx % (DIM * DIM / 4);
    float4 s = make_float4(0.f, 0.f, 0.f, 0.f);
    #pragma unroll
    for (int p = 0; p < NSPLIT; p++) {
        const float4 tv = *(const float4*)&g_partial[(((size_t)h * NSPLIT + p) * DIM * DIM) + e * 4];
        s.x += tv.x; s.y += tv.y; s.z += tv.z; s.w += tv.w;
    }
    *(float4*)&g_M[(size_t)idx * 4] = s;
}

// ---------------------------------------------------------------------------
// Kernel 3: out = Q @ M.  Block = 64 q-rows x 64 cols, 256 thr (8 warps).
// A = Q [q x d] -> pairs along d: Qhi/Qlo[q][dp], dp = d/2 (stride 36:
// banks 4g+t distinct).  B = M [d x n] -> pairs along d: Mhi/Mlo[dp][n]
// (stride 72: banks 8t+g distinct).
// Warps 4x2: (wid&3) -> 16-row group; (wid>>2) -> 32-col group (nt=4).
// Smem = 2*(64*36 + 32*72)*4*... = 36.9 KB (static-safe).
// ---------------------------------------------------------------------------
#define QSTR 36
#define QROWS 64
__global__ __launch_bounds__(256) void qm_gemm(const float* __restrict__ Qp,
                                               float* __restrict__ Op) {
    const int h  = blockIdx.x >> 6;            // 64 blocks per head
    const int r0 = (blockIdx.x & 63) * QROWS;

    __shared__ __align__(16) unsigned Qhi[QROWS][QSTR], Qlo[QROWS][QSTR];  // 18.4 KB
    __shared__ __align__(16) unsigned Mhi[32][KSTR],    Mlo[32][KSTR];     // 18.4 KB

    const int tid  = threadIdx.x;
    const int wid  = tid >> 5;
    const int lane = tid & 31;
    const int g = lane >> 2;
    const int t = lane & 3;
    const int rw = (wid & 3) * 16;     // q-row group of 16
    const int c0 = (wid >> 2) * 32;    // out col group of 32

    const float* Qh = Qp + ((size_t)h * SEQ + r0) * DIM;
    const float* Mh = g_M + (size_t)h * DIM * DIM;

    // stage Q: 64 rows x 32 dp words; slots: row = i>>3, dp4 = (i&7)*4 -> 512 slots
    #pragma unroll
    for (int s = tid; s < QROWS * 8; s += 256) {
        const int r   = s >> 3;
        const int dp4 = (s & 7) << 2;           // dp..dp+3 -> d = 2*dp4 .. 2*dp4+7
        const float4 qa = *(const float4*)&Qh[(size_t)r * DIM + 2 * dp4];
        const float4 qb = *(const float4*)&Qh[(size_t)r * DIM + 2 * dp4 + 4];
        uint4 whi, wlo;
        pack2(qa.x, qa.y, whi.x, wlo.x);
        pack2(qa.z, qa.w, whi.y, wlo.y);
        pack2(qb.x, qb.y, whi.z, wlo.z);
        pack2(qb.z, qb.w, whi.w, wlo.w);
        *(uint4*)&Qhi[r][dp4] = whi;
        *(uint4*)&Qlo[r][dp4] = wlo;
    }
    // stage M: 32 dp rows x 64 cols; slots: dp = i>>4, c4 = (i&15)*4 -> 512 slots
    #pragma unroll
    for (int s = tid; s < 32 * 16; s += 256) {
        const int dp = s >> 4;
        const int c4 = (s & 15) << 2;
        const float4 m0 = *(const float4*)&Mh[(2 * dp) * DIM + c4];
        const float4 m1 = *(const float4*)&Mh[(2 * dp + 1) * DIM + c4];
        uint4 whi, wlo;
        pack2(m0.x, m1.x, whi.x, wlo.x);
        pack2(m0.y, m1.y, whi.y, wlo.y);
        pack2(m0.z, m1.z, whi.z, wlo.z);
        pack2(m0.w, m1.w, whi.w, wlo.w);
        *(uint4*)&Mhi[dp][c4] = whi;
        *(uint4*)&Mlo[dp][c4] = wlo;
    }
    __syncthreads();

    float acc[4][4] = {};

    #pragma unroll
    for (int ks = 0; ks < 4; ks++) {            // four k16 slabs (d = 64)
        const int db = ks * 8;                  // dp base
        unsigned ah[4], al[4];
        ah[0] = Qhi[rw + g][db + t];         al[0] = Qlo[rw + g][db + t];
        ah[1] = Qhi[rw + g + 8][db + t];     al[1] = Qlo[rw + g + 8][db + t];
        ah[2] = Qhi[rw + g][db + t + 4];     al[2] = Qlo[rw + g][db + t + 4];
        ah[3] = Qhi[rw + g + 8][db + t + 4]; al[3] = Qlo[rw + g + 8][db + t + 4];
        #pragma unroll
        for (int nt = 0; nt < 4; nt++) {
            const int col = c0 + nt * 8 + g;
            unsigned bh[2], bl[2];
            bh[0] = Mhi[db + t][col];     bl[0] = Mlo[db + t][col];
            bh[1] = Mhi[db + t + 4][col]; bl[1] = Mlo[db + t + 4][col];
            mma_x3(acc[nt], ah, al, bh, bl);
        }
    }

    float* Oh = Op + ((size_t)h * SEQ + r0) * DIM;
    #pragma unroll
    for (int nt = 0; nt < 4; nt++) {
        const int col = c0 + nt * 8 + 2 * t;
        const int row = rw + g;
        *(float2*)&Oh[(size_t)row * DIM + col]       = make_float2(acc[nt][0], acc[nt][1]);
        *(float2*)&Oh[(size_t)(row + 8) * DIM + col] = make_float2(acc[nt][2], acc[nt][3]);
    }
}

// ---------------------------------------------------------------------------
extern "C" void kernel_launch(void* const* d_in, const int* in_sizes, int n_in,
                              void* d_out, int out_size) {
    const float* q = (const float*)d_in[0];
    const float* k = (const float*)d_in[1];
    const float* v = (const float*)d_in[2];
    float* out = (float*)d_out;

    ktv_partial<<<HEADS * NSPLIT, 256>>>(k, v);
    reduce_m<<<(HEADS * DIM * DIM / 4 + 255) / 256, 256>>>();
    qm_gemm<<<HEADS * (SEQ / QROWS), 256>>>(q, out);
}